// round 13
// baseline (speedup 1.0000x reference)
#include <cuda_runtime.h>
#include <cuda_fp16.h>
#include <cstdint>

#define B_   32
#define N_   512
#define K1_  256
#define O_   256
#define EPSF 1e-8f

// ---- GEMM tiling: CTA 128m x 128n, warp tile 32x32 (16 warps), KC=32 -------
#define KC      32
#define A_ROW   80
#define A_PLANE (128 * A_ROW)              // 10240
#define B_ROW   272
#define B_PLANE (KC * B_ROW)               // 8704
#define AUX_SZ  2048
#define STAGE   (A_PLANE + B_PLANE)        // 18944
#define OFF_A   0
#define OFF_B   A_PLANE
#define NSTAGE  4
#define SMEM_TOTAL (AUX_SZ + NSTAGE * STAGE)   // 77824 -> 2 CTAs/SM

#define GRID_CTAS 296
#define TOTAL_ITEMS 1344

// ---- scratch ----------------------------------------------------------------
__device__ __align__(16) float    g_dis[B_ * N_];
__device__ __align__(16) uint32_t g_A16[B_ * N_ * N_ / 2];
__device__ __align__(16) uint32_t g_H16[B_ * N_ * K1_ / 2];
__device__ __align__(16) uint32_t g_HsH[B_ * N_ * O_ / 2];
__device__ __align__(16) uint32_t g_WtH[K1_ * O_ / 2];

// ---- dataflow counters (zeroed per launch by zero_flags) --------------------
__device__ int g_w16d;
__device__ int g_h16d;
__device__ int g_pAd[B_];
__device__ int g_g1d[B_];

// ---- helpers ----------------------------------------------------------------
__device__ __forceinline__ void ldsm_x4(uint32_t& r0, uint32_t& r1, uint32_t& r2,
                                        uint32_t& r3, uint32_t addr) {
    asm volatile("ldmatrix.sync.aligned.m8n8.x4.shared.b16 {%0,%1,%2,%3}, [%4];"
                 : "=r"(r0), "=r"(r1), "=r"(r2), "=r"(r3) : "r"(addr));
}
__device__ __forceinline__ void ldsm_x4t(uint32_t& r0, uint32_t& r1, uint32_t& r2,
                                         uint32_t& r3, uint32_t addr) {
    asm volatile("ldmatrix.sync.aligned.m8n8.x4.trans.shared.b16 {%0,%1,%2,%3}, [%4];"
                 : "=r"(r0), "=r"(r1), "=r"(r2), "=r"(r3) : "r"(addr));
}
__device__ __forceinline__ void mma16816(float* c,
                                         uint32_t a0, uint32_t a1, uint32_t a2, uint32_t a3,
                                         uint32_t b0, uint32_t b1) {
    asm volatile("mma.sync.aligned.m16n8k16.row.col.f32.f16.f16.f32 "
                 "{%0,%1,%2,%3}, {%4,%5,%6,%7}, {%8,%9}, {%0,%1,%2,%3};"
                 : "+f"(c[0]), "+f"(c[1]), "+f"(c[2]), "+f"(c[3])
                 : "r"(a0), "r"(a1), "r"(a2), "r"(a3), "r"(b0), "r"(b1));
}
__device__ __forceinline__ uint32_t packh2(float v0, float v1) {
    __half2 h = __floats2half2_rn(v0, v1);
    return *reinterpret_cast<uint32_t*>(&h);
}
__device__ __forceinline__ float2 unpackh2(uint32_t q) {
    __half2 h = *reinterpret_cast<__half2*>(&q);
    return __half22float2(h);
}
__device__ __forceinline__ void cpa16(uint32_t dst, const void* src) {
    asm volatile("cp.async.cg.shared.global [%0], [%1], 16;" :: "r"(dst), "l"(src));
}
#define CP_COMMIT() asm volatile("cp.async.commit_group;" ::: "memory")
#define CP_WAIT(n)  asm volatile("cp.async.wait_group %0;" :: "n"(n) : "memory")

__device__ __forceinline__ void wait1(int* p, int tgt, int tid) {
    if (tid == 0) { volatile int* vp = p; while (*vp < tgt) __nanosleep(128); }
    __syncthreads();
    __threadfence();
}
__device__ __forceinline__ void wait2(int* p1, int t1, int* p2, int t2, int tid) {
    if (tid == 0) {
        volatile int* v1 = p1; volatile int* v2 = p2;
        while (*v1 < t1 || *v2 < t2) __nanosleep(128);
    }
    __syncthreads();
    __threadfence();
}
__device__ __forceinline__ void signal(int* p, int tid) {
    __syncthreads();
    if (tid == 0) { __threadfence(); atomicAdd(p, 1); }
}

// per-chunk mma: KC=32 (2 k-halves), warp tile 32x32
__device__ __forceinline__ void chunk_mma32(float acc[2][4][4], uint32_t bufb,
                                            int wm, int wn, int lane) {
    const uint32_t arow = (uint32_t)((lane & 7) + ((lane >> 3) & 1) * 8);
#pragma unroll
    for (int kh = 0; kh < 2; kh++) {
        const uint32_t a_base = bufb + OFF_A + (wm * 32 + arow) * A_ROW
                              + kh * 32 + (lane >> 4) * 16;
        uint32_t a[2][4], bb[4][2];
#pragma unroll
        for (int mi = 0; mi < 2; mi++)
            ldsm_x4(a[mi][0], a[mi][1], a[mi][2], a[mi][3], a_base + mi * 16 * A_ROW);
#pragma unroll
        for (int p = 0; p < 2; p++) {
            const uint32_t baddr = bufb + OFF_B + (kh * 16 + (lane & 15)) * B_ROW
                                 + (wn * 32 + p * 16 + (lane >> 4) * 8) * 2;
            ldsm_x4t(bb[2 * p][0], bb[2 * p][1], bb[2 * p + 1][0], bb[2 * p + 1][1], baddr);
        }
#pragma unroll
        for (int mi = 0; mi < 2; mi++)
#pragma unroll
            for (int n = 0; n < 4; n++)
                mma16816(acc[mi][n], a[mi][0], a[mi][1], a[mi][2], a[mi][3],
                         bb[n][0], bb[n][1]);
    }
}

// ---------------------------------------------------------------------------
// work items
// ---------------------------------------------------------------------------
__device__ void do_prepA(const float* __restrict__ A, int b, int part, int tid) {
    int wid = tid >> 5, lane = tid & 31;
    int row0 = b * N_ + part * 32 + wid * 2;       // 16 warps x 2 rows = 32 rows
    const float4* a = reinterpret_cast<const float4*>(A + (size_t)row0 * N_);
    uint2* a16 = reinterpret_cast<uint2*>(g_A16);
    float s0 = 0.f, s1 = 0.f;
#pragma unroll
    for (int c = 0; c < 4; c++) {
        float4 v = a[lane + c * 32];
        float4 w = a[128 + lane + c * 32];
        s0 += (v.x + v.y) + (v.z + v.w);
        s1 += (w.x + w.y) + (w.z + w.w);
        a16[(size_t)row0 * 128 + lane + c * 32] =
            make_uint2(packh2(v.x, v.y), packh2(v.z, v.w));
        a16[(size_t)(row0 + 1) * 128 + lane + c * 32] =
            make_uint2(packh2(w.x, w.y), packh2(w.z, w.w));
    }
#pragma unroll
    for (int o = 16; o > 0; o >>= 1) {
        s0 += __shfl_xor_sync(0xffffffffu, s0, o);
        s1 += __shfl_xor_sync(0xffffffffu, s1, o);
    }
    if (lane == 0) {
        g_dis[row0]     = rsqrtf(s0 + 1.0f + EPSF);
        g_dis[row0 + 1] = rsqrtf(s1 + 1.0f + EPSF);
    }
    signal(&g_pAd[b], tid);
}

__device__ void do_W16(char* smem, const float* __restrict__ W, int idx, int tid) {
    float (*tile)[33] = reinterpret_cast<float(*)[33]>(smem);
    int k0 = (idx & 7) * 32, o0 = (idx >> 3) * 32;
    if (tid < 256) {
        int tx = tid & 31, ty = tid >> 5;
#pragma unroll
        for (int i = 0; i < 32; i += 8)
            tile[ty + i][tx] = W[(size_t)(o0 + ty + i) * K1_ + k0 + tx];
    }
    __syncthreads();
    if (tid < 256) {
        int txp = tid & 15, typ = tid >> 4;
#pragma unroll
        for (int i = 0; i < 32; i += 16) {
            int k = typ + i;
            g_WtH[((size_t)(k0 + k) * O_ + o0 + txp * 2) >> 1] =
                packh2(tile[txp * 2][k], tile[txp * 2 + 1][k]);
        }
    }
    signal(&g_w16d, tid);
}

__device__ void do_H16(const float* __restrict__ H, int idx, int tid) {
    const float4* h4 = reinterpret_cast<const float4*>(H) + (size_t)idx * 4096;
    uint4* h16 = reinterpret_cast<uint4*>(g_H16) + (size_t)idx * 2048;
#pragma unroll
    for (int it = 0; it < 4; it++) {
        int g = tid + it * 512;
        float4 f0 = h4[2 * g], f1 = h4[2 * g + 1];
        h16[g] = make_uint4(packh2(f0.x, f0.y), packh2(f0.z, f0.w),
                            packh2(f1.x, f1.y), packh2(f1.z, f1.w));
    }
    signal(&g_h16d, tid);
}

__device__ void do_gemm1(char* smem, uint32_t sb, const float* __restrict__ bias,
                         int b, int q, int o, int t) {
    const int lane = t & 31, wid = t >> 5;
    const int wm = wid >> 2, wn = wid & 3;
    const int bm = b * N_ + q * 128;
    const int bn = o * 128;

    float* bias_s = reinterpret_cast<float*>(smem);
    float* dis_s  = reinterpret_cast<float*>(smem + 1024);
    if (t < 128) bias_s[t] = bias[bn + t];

    wait2(&g_h16d, 256, &g_w16d, 64, t);

    const char* srcA = reinterpret_cast<const char*>(g_H16)
                     + (size_t)(bm + (t >> 2)) * 512 + (t & 3) * 16;
    const char* srcB = reinterpret_cast<const char*>(g_WtH)
                     + (size_t)(t >> 4) * 512 + (size_t)bn * 2 + (t & 15) * 16;
    const uint32_t soa = sb + AUX_SZ + OFF_A + (t >> 2) * A_ROW + (t & 3) * 16;
    const uint32_t sob = sb + AUX_SZ + OFF_B + (t >> 4) * B_ROW + (t & 15) * 16;

    float acc[2][4][4];
#pragma unroll
    for (int i = 0; i < 2; i++)
#pragma unroll
        for (int j = 0; j < 4; j++)
#pragma unroll
            for (int e = 0; e < 4; e++) acc[i][j][e] = 0.f;

    const int S = K1_ / KC;  // 8
#pragma unroll
    for (int p = 0; p < 3; p++) {
        cpa16(soa + p * STAGE, srcA + p * 64);
        cpa16(sob + p * STAGE, srcB + (size_t)p * 16384);
        CP_COMMIT();
    }
    for (int s = 0; s < S; s++) {
        CP_WAIT(2);
        __syncthreads();
        if (s + 3 < S) {
            uint32_t st = (uint32_t)((s + 3) & 3) * STAGE;
            cpa16(soa + st, srcA + (s + 3) * 64);
            cpa16(sob + st, srcB + (size_t)(s + 3) * 16384);
        }
        CP_COMMIT();
        chunk_mma32(acc, sb + AUX_SZ + (uint32_t)(s & 3) * STAGE, wm, wn, lane);
    }
    CP_WAIT(0);

    wait1(&g_pAd[b], 16, t);                 // dis needed only now
    if (t < 128) dis_s[t] = g_dis[bm + t];
    __syncthreads();

    const int g = lane >> 2, i4 = lane & 3;
#pragma unroll
    for (int mi = 0; mi < 2; mi++) {
        int r0 = wm * 32 + mi * 16 + g;
        float d0 = dis_s[r0], d1 = dis_s[r0 + 8];
        size_t base0 = (size_t)(bm + r0) * O_ + bn;
        size_t base1 = base0 + 8 * O_;
#pragma unroll
        for (int n = 0; n < 4; n++) {
            int oo = wn * 32 + n * 8 + i4 * 2;
            g_HsH[(base0 + oo) >> 1] = packh2((acc[mi][n][0] + bias_s[oo]) * d0,
                                              (acc[mi][n][1] + bias_s[oo + 1]) * d0);
            g_HsH[(base1 + oo) >> 1] = packh2((acc[mi][n][2] + bias_s[oo]) * d1,
                                              (acc[mi][n][3] + bias_s[oo + 1]) * d1);
        }
    }
    signal(&g_g1d[b], t);
}

__device__ void do_gemm2(char* smem, uint32_t sb, const float* __restrict__ mask,
                         float* __restrict__ out, int b, int itile, int o, int t) {
    const int lane = t & 31, wid = t >> 5;
    const int wm = wid >> 2, wn = wid & 3;
    const int i0 = itile * 128;
    const int bn = o * 128;

    wait2(&g_g1d[b], 8, &g_pAd[b], 16, t);

    float* mdis_s = reinterpret_cast<float*>(smem);
    if (t < 128) mdis_s[t] = mask[b * N_ + i0 + t] * g_dis[b * N_ + i0 + t];

    const char* srcA = reinterpret_cast<const char*>(g_A16)
                     + ((size_t)b * N_ + i0 + (t >> 2)) * 1024 + (t & 3) * 16;
    const char* srcB = reinterpret_cast<const char*>(g_HsH)
                     + ((size_t)b * N_ + (t >> 4)) * 512 + (size_t)bn * 2 + (t & 15) * 16;
    const uint32_t soa = sb + AUX_SZ + OFF_A + (t >> 2) * A_ROW + (t & 3) * 16;
    const uint32_t sob = sb + AUX_SZ + OFF_B + (t >> 4) * B_ROW + (t & 15) * 16;

    float acc[2][4][4];
#pragma unroll
    for (int i = 0; i < 2; i++)
#pragma unroll
        for (int j = 0; j < 4; j++)
#pragma unroll
            for (int e = 0; e < 4; e++) acc[i][j][e] = 0.f;

    const int S = N_ / KC;  // 16
#pragma unroll
    for (int p = 0; p < 3; p++) {
        cpa16(soa + p * STAGE, srcA + p * 64);
        cpa16(sob + p * STAGE, srcB + (size_t)p * 16384);
        CP_COMMIT();
    }
    for (int s = 0; s < S; s++) {
        CP_WAIT(2);
        __syncthreads();
        if (s + 3 < S) {
            uint32_t st = (uint32_t)((s + 3) & 3) * STAGE;
            cpa16(soa + st, srcA + (s + 3) * 64);
            cpa16(sob + st, srcB + (size_t)(s + 3) * 16384);
        }
        CP_COMMIT();
        chunk_mma32(acc, sb + AUX_SZ + (uint32_t)(s & 3) * STAGE, wm, wn, lane);
    }
    CP_WAIT(0);
    __syncthreads();

    const int g = lane >> 2, i4 = lane & 3;
#pragma unroll
    for (int mi = 0; mi < 2; mi++) {
        int r0 = wm * 32 + mi * 16 + g;
        float md0 = mdis_s[r0], md1 = mdis_s[r0 + 8];
        size_t row0 = ((size_t)b * N_ + i0 + r0) * O_ + bn;
        size_t row1 = row0 + 8 * O_;
#pragma unroll
        for (int n = 0; n < 4; n++) {
            int oo = wn * 32 + n * 8 + i4 * 2;
            float2 s0 = unpackh2(g_HsH[(row0 + oo) >> 1]);
            float2 s1 = unpackh2(g_HsH[(row1 + oo) >> 1]);
            out[row0 + oo]     = fmaxf(0.f, md0 * (acc[mi][n][0] + s0.x));
            out[row0 + oo + 1] = fmaxf(0.f, md0 * (acc[mi][n][1] + s0.y));
            out[row1 + oo]     = fmaxf(0.f, md1 * (acc[mi][n][2] + s1.x));
            out[row1 + oo + 1] = fmaxf(0.f, md1 * (acc[mi][n][3] + s1.y));
        }
    }
    __syncthreads();
}

// ---------------------------------------------------------------------------
__global__ void zero_flags() {
    int t = threadIdx.x;
    if (t == 0) { g_w16d = 0; g_h16d = 0; }
    if (t < B_) { g_pAd[t] = 0; g_g1d[t] = 0; }
}

// Item queue (positions strictly order dependencies):
//   [0,16):    prepA[0]          [16,32):  prepA[1]
//   [32,96):   W16 (64)          [96,352): H16 (256)
//   [352+32b + r), b=0..29: r<16 -> prepA[b+2], r<24 -> gemm1[b], else gemm2[b]
//   [1312+16j + r), j=0..1 (b=30+j): r<8 -> gemm1[b], else gemm2[b]
__global__ __launch_bounds__(512, 2)
void fused_kernel(const float* __restrict__ A, const float* __restrict__ H,
                  const float* __restrict__ W, const float* __restrict__ bias,
                  const float* __restrict__ mask, float* __restrict__ out) {
    extern __shared__ char smem[];
    const uint32_t sb = (uint32_t)__cvta_generic_to_shared(smem);
    const int t = threadIdx.x;

    for (int item = blockIdx.x; item < TOTAL_ITEMS; item += gridDim.x) {
        if (item < 16)        do_prepA(A, 0, item, t);
        else if (item < 32)   do_prepA(A, 1, item - 16, t);
        else if (item < 96)   do_W16(smem, W, item - 32, t);
        else if (item < 352)  do_H16(H, item - 96, t);
        else {
            int j = item - 352;
            if (j < 960) {
                int b = j >> 5, r = j & 31;
                if (r < 16)      do_prepA(A, b + 2, r, t);
                else if (r < 24) do_gemm1(smem, sb, bias, b, (r - 16) >> 1, (r - 16) & 1, t);
                else             do_gemm2(smem, sb, mask, out, b, (r - 24) >> 1, (r - 24) & 1, t);
            } else {
                int j2 = j - 960;
                int b = 30 + (j2 >> 4), r = j2 & 15;
                if (r < 8) do_gemm1(smem, sb, bias, b, r >> 1, r & 1, t);
                else       do_gemm2(smem, sb, mask, out, b, (r - 8) >> 1, (r - 8) & 1, t);
            }
        }
        __syncthreads();
    }
}

// ---------------------------------------------------------------------------
extern "C" void kernel_launch(void* const* d_in, const int* in_sizes, int n_in,
                              void* d_out, int out_size) {
    const float* H    = (const float*)d_in[0];
    const float* A    = (const float*)d_in[1];
    const float* mask = (const float*)d_in[2];
    const float* W    = (const float*)d_in[3];
    const float* bias = (const float*)d_in[4];
    float* out = (float*)d_out;

    cudaFuncSetAttribute(fused_kernel, cudaFuncAttributeMaxDynamicSharedMemorySize,
                         SMEM_TOTAL);

    zero_flags<<<1, 256>>>();
    fused_kernel<<<GRID_CTAS, 512, SMEM_TOTAL>>>(A, H, W, bias, mask, out);
}

// round 14
// speedup vs baseline: 1.6006x; 1.6006x over previous
#include <cuda_runtime.h>
#include <cuda_fp16.h>
#include <cstdint>

#define B_   32
#define N_   512
#define K1_  256
#define O_   256
#define EPSF 1e-8f

// ---- GEMM tiling: CTA 128m x 128n, warp tile 32x32 (16 warps), KC=32 -------
#define KC      32
#define A_ROW   80
#define A_PLANE (128 * A_ROW)              // 10240
#define B_ROW   272
#define B_PLANE (KC * B_ROW)               // 8704
#define AUX_SZ  2048
#define STAGE   (A_PLANE + B_PLANE)        // 18944
#define OFF_A   0
#define OFF_B   A_PLANE
#define NSTAGE  4
#define SMEM_TOTAL (AUX_SZ + NSTAGE * STAGE)   // 77824 -> 2 CTAs/SM

// ---- scratch ----------------------------------------------------------------
__device__ __align__(16) float    g_dis[B_ * N_];
__device__ __align__(16) uint32_t g_A16[B_ * N_ * N_ / 2];   // A fp16 [b][i][j]
__device__ __align__(16) uint32_t g_H16[B_ * N_ * K1_ / 2];  // H fp16 [m][k]
__device__ __align__(16) uint32_t g_HsH[B_ * N_ * O_ / 2];   // Hs fp16 [b][j][o]
__device__ __align__(16) uint32_t g_WtH[K1_ * O_ / 2];       // W^T fp16 [k][o]
__device__ int g_pA_total;                                    // prepA completions

// ---- helpers ----------------------------------------------------------------
__device__ __forceinline__ void ldsm_x4(uint32_t& r0, uint32_t& r1, uint32_t& r2,
                                        uint32_t& r3, uint32_t addr) {
    asm volatile("ldmatrix.sync.aligned.m8n8.x4.shared.b16 {%0,%1,%2,%3}, [%4];"
                 : "=r"(r0), "=r"(r1), "=r"(r2), "=r"(r3) : "r"(addr));
}
__device__ __forceinline__ void ldsm_x4t(uint32_t& r0, uint32_t& r1, uint32_t& r2,
                                         uint32_t& r3, uint32_t addr) {
    asm volatile("ldmatrix.sync.aligned.m8n8.x4.trans.shared.b16 {%0,%1,%2,%3}, [%4];"
                 : "=r"(r0), "=r"(r1), "=r"(r2), "=r"(r3) : "r"(addr));
}
__device__ __forceinline__ void mma16816(float* c,
                                         uint32_t a0, uint32_t a1, uint32_t a2, uint32_t a3,
                                         uint32_t b0, uint32_t b1) {
    asm volatile("mma.sync.aligned.m16n8k16.row.col.f32.f16.f16.f32 "
                 "{%0,%1,%2,%3}, {%4,%5,%6,%7}, {%8,%9}, {%0,%1,%2,%3};"
                 : "+f"(c[0]), "+f"(c[1]), "+f"(c[2]), "+f"(c[3])
                 : "r"(a0), "r"(a1), "r"(a2), "r"(a3), "r"(b0), "r"(b1));
}
__device__ __forceinline__ uint32_t packh2(float v0, float v1) {
    __half2 h = __floats2half2_rn(v0, v1);
    return *reinterpret_cast<uint32_t*>(&h);
}
__device__ __forceinline__ float2 unpackh2(uint32_t q) {
    __half2 h = *reinterpret_cast<__half2*>(&q);
    return __half22float2(h);
}
__device__ __forceinline__ void cpa16(uint32_t dst, const void* src) {
    asm volatile("cp.async.cg.shared.global [%0], [%1], 16;" :: "r"(dst), "l"(src));
}
#define CP_COMMIT() asm volatile("cp.async.commit_group;" ::: "memory")
#define CP_WAIT(n)  asm volatile("cp.async.wait_group %0;" :: "n"(n) : "memory")

// per-chunk mma: KC=32 (2 k-halves), warp tile 32x32
__device__ __forceinline__ void chunk_mma32(float acc[2][4][4], uint32_t bufb,
                                            int wm, int wn, int lane) {
    const uint32_t arow = (uint32_t)((lane & 7) + ((lane >> 3) & 1) * 8);
#pragma unroll
    for (int kh = 0; kh < 2; kh++) {
        const uint32_t a_base = bufb + OFF_A + (wm * 32 + arow) * A_ROW
                              + kh * 32 + (lane >> 4) * 16;
        uint32_t a[2][4], bb[4][2];
#pragma unroll
        for (int mi = 0; mi < 2; mi++)
            ldsm_x4(a[mi][0], a[mi][1], a[mi][2], a[mi][3], a_base + mi * 16 * A_ROW);
#pragma unroll
        for (int p = 0; p < 2; p++) {
            const uint32_t baddr = bufb + OFF_B + (kh * 16 + (lane & 15)) * B_ROW
                                 + (wn * 32 + p * 16 + (lane >> 4) * 8) * 2;
            ldsm_x4t(bb[2 * p][0], bb[2 * p][1], bb[2 * p + 1][0], bb[2 * p + 1][1], baddr);
        }
#pragma unroll
        for (int mi = 0; mi < 2; mi++)
#pragma unroll
            for (int n = 0; n < 4; n++)
                mma16816(acc[mi][n], a[mi][0], a[mi][1], a[mi][2], a[mi][3],
                         bb[n][0], bb[n][1]);
    }
}

// ---------------------------------------------------------------------------
// prep0: [0,256): H -> H16 (64 rows each); [256,320): W^T tiles; bid 0 zeroes.
// ---------------------------------------------------------------------------
__global__ __launch_bounds__(256)
void prep0_kernel(const float* __restrict__ H, const float* __restrict__ W) {
    __shared__ float tile[32][33];
    const int t = threadIdx.x;
    if (blockIdx.x == 0 && t == 0) g_pA_total = 0;
    if (blockIdx.x < 256) {
        int hb = blockIdx.x;                   // 64 H rows per block
        const float4* h4 = reinterpret_cast<const float4*>(H) + (size_t)hb * 4096;
        uint4* h16 = reinterpret_cast<uint4*>(g_H16) + (size_t)hb * 2048;
#pragma unroll
        for (int it = 0; it < 8; it++) {
            int gidx = t + it * 256;
            float4 f0 = h4[2 * gidx], f1 = h4[2 * gidx + 1];
            h16[gidx] = make_uint4(packh2(f0.x, f0.y), packh2(f0.z, f0.w),
                                   packh2(f1.x, f1.y), packh2(f1.z, f1.w));
        }
    } else {
        int idx = blockIdx.x - 256;            // 64 tiles: 8x8
        int k0 = (idx & 7) * 32, o0 = (idx >> 3) * 32;
        int tx = t & 31, ty = t >> 5;          // (32, 8)
#pragma unroll
        for (int i = 0; i < 32; i += 8)
            tile[ty + i][tx] = W[(size_t)(o0 + ty + i) * K1_ + k0 + tx];
        __syncthreads();
        int txp = t & 15, typ = t >> 4;        // (16, 16)
#pragma unroll
        for (int i = 0; i < 32; i += 16) {
            int k = typ + i;
            g_WtH[((size_t)(k0 + k) * O_ + o0 + txp * 2) >> 1] =
                packh2(tile[txp * 2][k], tile[txp * 2 + 1][k]);
        }
    }
}

// ---------------------------------------------------------------------------
// fused1: grid 512, 512 thr. Even bids: gemm1 tile. Odd bids: prepA (64 rows).
// ---------------------------------------------------------------------------
__global__ __launch_bounds__(512, 2)
void fused1_kernel(const float* __restrict__ A, const float* __restrict__ bias) {
    extern __shared__ char smem[];
    const int t = threadIdx.x;

    if (blockIdx.x & 1) {
        // ---- prepA: deg + A->fp16 for 64 rows ----
        const int idx = blockIdx.x >> 1;           // 0..255
        const int wid = t >> 5, lane = t & 31;
        const int row0 = idx * 64 + wid * 4;       // 16 warps x 4 rows
        const float4* a = reinterpret_cast<const float4*>(A + (size_t)row0 * N_);
        uint2* a16 = reinterpret_cast<uint2*>(g_A16);
        float s[4] = {0.f, 0.f, 0.f, 0.f};
#pragma unroll
        for (int c = 0; c < 4; c++)
#pragma unroll
            for (int r = 0; r < 4; r++) {
                float4 v = a[(size_t)r * 128 + lane + c * 32];
                s[r] += (v.x + v.y) + (v.z + v.w);
                a16[(size_t)(row0 + r) * 128 + lane + c * 32] =
                    make_uint2(packh2(v.x, v.y), packh2(v.z, v.w));
            }
#pragma unroll
        for (int o = 16; o > 0; o >>= 1)
#pragma unroll
            for (int r = 0; r < 4; r++) s[r] += __shfl_xor_sync(0xffffffffu, s[r], o);
        if (lane == 0)
#pragma unroll
            for (int r = 0; r < 4; r++) g_dis[row0 + r] = rsqrtf(s[r] + 1.0f + EPSF);
        __syncthreads();
        if (t == 0) { __threadfence(); atomicAdd(&g_pA_total, 1); }
        return;
    }

    // ---- gemm1 tile ----
    const uint32_t sb = (uint32_t)__cvta_generic_to_shared(smem);
    const int lane = t & 31, wid = t >> 5;
    const int wm = wid >> 2, wn = wid & 3;
    const int tile = blockIdx.x >> 1;              // 0..255
    const int bm = (tile >> 1) * 128;
    const int bn = (tile & 1) * 128;

    float* bias_s = reinterpret_cast<float*>(smem);
    float* dis_s  = reinterpret_cast<float*>(smem + 1024);
    if (t < 128) bias_s[t] = bias[bn + t];

    const char* srcA = reinterpret_cast<const char*>(g_H16)
                     + (size_t)(bm + (t >> 2)) * 512 + (t & 3) * 16;
    const char* srcB = reinterpret_cast<const char*>(g_WtH)
                     + (size_t)(t >> 4) * 512 + (size_t)bn * 2 + (t & 15) * 16;
    const uint32_t soa = sb + AUX_SZ + OFF_A + (t >> 2) * A_ROW + (t & 3) * 16;
    const uint32_t sob = sb + AUX_SZ + OFF_B + (t >> 4) * B_ROW + (t & 15) * 16;

    float acc[2][4][4];
#pragma unroll
    for (int i = 0; i < 2; i++)
#pragma unroll
        for (int j = 0; j < 4; j++)
#pragma unroll
            for (int e = 0; e < 4; e++) acc[i][j][e] = 0.f;

    const int S = K1_ / KC;  // 8
#pragma unroll
    for (int p = 0; p < 3; p++) {
        cpa16(soa + p * STAGE, srcA + p * 64);
        cpa16(sob + p * STAGE, srcB + (size_t)p * 16384);
        CP_COMMIT();
    }
    for (int s = 0; s < S; s++) {
        CP_WAIT(2);
        __syncthreads();
        if (s + 3 < S) {
            uint32_t st = (uint32_t)((s + 3) & 3) * STAGE;
            cpa16(soa + st, srcA + (s + 3) * 64);
            cpa16(sob + st, srcB + (size_t)(s + 3) * 16384);
        }
        CP_COMMIT();
        chunk_mma32(acc, sb + AUX_SZ + (uint32_t)(s & 3) * STAGE, wm, wn, lane);
    }
    CP_WAIT(0);

    // wait for ALL prepA (dis ready), then load dis for this m-tile
    if (t == 0) {
        volatile int* vp = &g_pA_total;
        while (*vp < 256) __nanosleep(64);
    }
    __syncthreads();
    __threadfence();
    if (t < 128) dis_s[t] = g_dis[bm + t];
    __syncthreads();

    const int g = lane >> 2, i4 = lane & 3;
#pragma unroll
    for (int mi = 0; mi < 2; mi++) {
        int r0 = wm * 32 + mi * 16 + g;
        float d0 = dis_s[r0], d1 = dis_s[r0 + 8];
        size_t base0 = (size_t)(bm + r0) * O_ + bn;
        size_t base1 = base0 + 8 * O_;
#pragma unroll
        for (int n = 0; n < 4; n++) {
            int o = wn * 32 + n * 8 + i4 * 2;
            g_HsH[(base0 + o) >> 1] = packh2((acc[mi][n][0] + bias_s[o]) * d0,
                                             (acc[mi][n][1] + bias_s[o + 1]) * d0);
            g_HsH[(base1 + o) >> 1] = packh2((acc[mi][n][2] + bias_s[o]) * d1,
                                             (acc[mi][n][3] + bias_s[o + 1]) * d1);
        }
    }
}

// ---------------------------------------------------------------------------
// GEMM2: out[b,i,o] = relu(mask*dis_i*(sum_j A[i,j] Hs[j,o] + Hs[i,o])).
// CTA 128x128, 512 thr, grid (4, 2, 32). K=512 -> 16 chunks of 32.
// ---------------------------------------------------------------------------
__global__ __launch_bounds__(512, 2)
void gemm2_mma(const float* __restrict__ mask, float* __restrict__ out) {
    extern __shared__ char smem[];
    const uint32_t sb = (uint32_t)__cvta_generic_to_shared(smem);
    const int t = threadIdx.x, lane = t & 31, wid = t >> 5;
    const int wm = wid >> 2, wn = wid & 3;
    const int i0 = blockIdx.x * 128;
    const int bn = blockIdx.y * 128;
    const int b  = blockIdx.z;

    float* mdis_s = reinterpret_cast<float*>(smem);   // 128 f
    if (t < 128) mdis_s[t] = mask[b * N_ + i0 + t] * g_dis[b * N_ + i0 + t];

    const char* srcA = reinterpret_cast<const char*>(g_A16)
                     + ((size_t)b * N_ + i0 + (t >> 2)) * 1024 + (t & 3) * 16;
    const char* srcB = reinterpret_cast<const char*>(g_HsH)
                     + ((size_t)b * N_ + (t >> 4)) * 512 + (size_t)bn * 2 + (t & 15) * 16;
    const uint32_t soa = sb + AUX_SZ + OFF_A + (t >> 2) * A_ROW + (t & 3) * 16;
    const uint32_t sob = sb + AUX_SZ + OFF_B + (t >> 4) * B_ROW + (t & 15) * 16;

    float acc[2][4][4];
#pragma unroll
    for (int i = 0; i < 2; i++)
#pragma unroll
        for (int j = 0; j < 4; j++)
#pragma unroll
            for (int e = 0; e < 4; e++) acc[i][j][e] = 0.f;

    const int S = N_ / KC;  // 16
#pragma unroll
    for (int p = 0; p < 3; p++) {
        cpa16(soa + p * STAGE, srcA + p * 64);
        cpa16(sob + p * STAGE, srcB + (size_t)p * 16384);
        CP_COMMIT();
    }
    for (int s = 0; s < S; s++) {
        CP_WAIT(2);
        __syncthreads();
        if (s + 3 < S) {
            uint32_t st = (uint32_t)((s + 3) & 3) * STAGE;
            cpa16(soa + st, srcA + (s + 3) * 64);
            cpa16(sob + st, srcB + (size_t)(s + 3) * 16384);
        }
        CP_COMMIT();
        chunk_mma32(acc, sb + AUX_SZ + (uint32_t)(s & 3) * STAGE, wm, wn, lane);
    }

    const int g = lane >> 2, i4 = lane & 3;
#pragma unroll
    for (int mi = 0; mi < 2; mi++) {
        int r0 = wm * 32 + mi * 16 + g;
        float md0 = mdis_s[r0], md1 = mdis_s[r0 + 8];
        size_t row0 = ((size_t)b * N_ + i0 + r0) * O_ + bn;
        size_t row1 = row0 + 8 * O_;
#pragma unroll
        for (int n = 0; n < 4; n++) {
            int o = wn * 32 + n * 8 + i4 * 2;
            float2 s0 = unpackh2(g_HsH[(row0 + o) >> 1]);
            float2 s1 = unpackh2(g_HsH[(row1 + o) >> 1]);
            out[row0 + o]     = fmaxf(0.f, md0 * (acc[mi][n][0] + s0.x));
            out[row0 + o + 1] = fmaxf(0.f, md0 * (acc[mi][n][1] + s0.y));
            out[row1 + o]     = fmaxf(0.f, md1 * (acc[mi][n][2] + s1.x));
            out[row1 + o + 1] = fmaxf(0.f, md1 * (acc[mi][n][3] + s1.y));
        }
    }
}

// ---------------------------------------------------------------------------
extern "C" void kernel_launch(void* const* d_in, const int* in_sizes, int n_in,
                              void* d_out, int out_size) {
    const float* H    = (const float*)d_in[0];
    const float* A    = (const float*)d_in[1];
    const float* mask = (const float*)d_in[2];
    const float* W    = (const float*)d_in[3];
    const float* bias = (const float*)d_in[4];
    float* out = (float*)d_out;

    cudaFuncSetAttribute(fused1_kernel, cudaFuncAttributeMaxDynamicSharedMemorySize, SMEM_TOTAL);
    cudaFuncSetAttribute(gemm2_mma, cudaFuncAttributeMaxDynamicSharedMemorySize, SMEM_TOTAL);

    prep0_kernel<<<320, 256>>>(H, W);
    fused1_kernel<<<512, 512, SMEM_TOTAL>>>(A, bias);
    gemm2_mma<<<dim3(4, 2, B_), 512, SMEM_TOTAL>>>(mask, out);
}